// round 4
// baseline (speedup 1.0000x reference)
#include <cuda_runtime.h>
#include <math.h>

#define B_  2
#define S_  2048
#define D_  1024
#define H_  16
#define HD_ 64
#define M_  (B_ * S_)        // 4096
#define BHS (B_ * H_ * S_ * HD_)

// Scratch (device globals — no allocation inside kernel_launch)
__device__ float g_q[BHS];
__device__ float g_k[BHS];
__device__ float g_v[BHS];
__device__ float g_ctx[M_ * D_];

// ---------------------------------------------------------------------------
// Tiled SGEMM: C[M,N] = A[M,K] @ W + bias[n]
// HEADWISE=true : W is [H, K, 64] (per-head weights), output scattered to
//                 [B,H,S,HD] layout. BN=64 == HD so each N-block is one head.
// HEADWISE=false: W is [K, N] row-major, output row-major [M,N].
// 64x64 tile, BK=16, 256 threads, 4x4 per-thread microtile.
// ---------------------------------------------------------------------------
template <bool HEADWISE>
__global__ void gemm64_kernel(const float* __restrict__ A,
                              const float* __restrict__ W,
                              const float* __restrict__ bias,
                              float* __restrict__ C,
                              int K, int N) {
    __shared__ float As[64][17];   // padded
    __shared__ float Bs[16][65];   // padded

    const int tid = threadIdx.x;
    const int tx  = tid & 15;
    const int ty  = tid >> 4;
    const int m0  = blockIdx.x * 64;
    const int n0  = blockIdx.y * 64;

    float acc[4][4] = {};

    for (int kt = 0; kt < K; kt += 16) {
        // Load A tile 64x16
        #pragma unroll
        for (int i = tid; i < 64 * 16; i += 256) {
            int r = i >> 4, c = i & 15;
            As[r][c] = A[(size_t)(m0 + r) * K + kt + c];
        }
        // Load B tile 16x64
        #pragma unroll
        for (int i = tid; i < 16 * 64; i += 256) {
            int r = i >> 6, c = i & 63;
            int n = n0 + c;
            float w;
            if (HEADWISE) {
                // W[h, k, kk] with h = n/64, kk = n%64
                w = W[(size_t)(n >> 6) * K * 64 + (size_t)(kt + r) * 64 + (n & 63)];
            } else {
                w = W[(size_t)(kt + r) * N + n];
            }
            Bs[r][c] = w;
        }
        __syncthreads();

        #pragma unroll
        for (int kk = 0; kk < 16; kk++) {
            float a[4], b[4];
            #pragma unroll
            for (int i = 0; i < 4; i++) a[i] = As[ty * 4 + i][kk];
            #pragma unroll
            for (int j = 0; j < 4; j++) b[j] = Bs[kk][tx * 4 + j];
            #pragma unroll
            for (int i = 0; i < 4; i++)
                #pragma unroll
                for (int j = 0; j < 4; j++)
                    acc[i][j] = fmaf(a[i], b[j], acc[i][j]);
        }
        __syncthreads();
    }

    // Epilogue
    #pragma unroll
    for (int i = 0; i < 4; i++) {
        int m = m0 + ty * 4 + i;
        #pragma unroll
        for (int j = 0; j < 4; j++) {
            int n = n0 + tx * 4 + j;
            float v = acc[i][j] + bias[n];
            if (HEADWISE) {
                int b = m / S_;
                int s = m - b * S_;
                int h = n >> 6;
                int k = n & 63;
                C[(((size_t)(b * H_ + h)) * S_ + s) * HD_ + k] = v;
            } else {
                C[(size_t)m * N + n] = v;
            }
        }
    }
}

// ---------------------------------------------------------------------------
// Flash attention: per (b,h), 64 query rows per CTA, stream 64-row K/V tiles.
// Online softmax; row stats reduced with width-16 shuffles (ty-group = 16
// contiguous lanes). ctx written in [B, S, H*HD] layout.
// ---------------------------------------------------------------------------
#define AT_PAD 65
#define ATTN_SMEM_FLOATS (4 * 64 * AT_PAD)

__global__ void attn_kernel(float* __restrict__ ctx) {
    extern __shared__ float sm[];
    float* qs = sm;                    // [64][65]
    float* ks = qs + 64 * AT_PAD;      // [64][65]
    float* vs = ks + 64 * AT_PAD;      // [64][65]
    float* ps = vs + 64 * AT_PAD;      // [64][65]

    const int tid = threadIdx.x;
    const int tx  = tid & 15;
    const int ty  = tid >> 4;
    const int bh  = blockIdx.y;            // b*H + h
    const int b   = bh / H_;
    const int h   = bh - b * H_;
    const int s0  = blockIdx.x * 64;

    const float* Q = g_q + (size_t)bh * S_ * HD_;
    const float* K = g_k + (size_t)bh * S_ * HD_;
    const float* V = g_v + (size_t)bh * S_ * HD_;

    // Load Q tile
    #pragma unroll
    for (int i = tid; i < 64 * 64; i += 256) {
        int r = i >> 6, c = i & 63;
        qs[r * AT_PAD + c] = Q[(size_t)(s0 + r) * HD_ + c];
    }

    float m[4], l[4], acc[4][4];
    #pragma unroll
    for (int i = 0; i < 4; i++) {
        m[i] = -1e30f;
        l[i] = 0.f;
        #pragma unroll
        for (int j = 0; j < 4; j++) acc[i][j] = 0.f;
    }
    const float scale = 0.125f;  // 1/sqrt(64)

    for (int kt = 0; kt < S_; kt += 64) {
        __syncthreads();   // previous PV GEMM done before overwriting ks/vs
        #pragma unroll
        for (int i = tid; i < 64 * 64; i += 256) {
            int r = i >> 6, c = i & 63;
            ks[r * AT_PAD + c] = K[(size_t)(kt + r) * HD_ + c];
            vs[r * AT_PAD + c] = V[(size_t)(kt + r) * HD_ + c];
        }
        __syncthreads();

        // S = Q K^T  (4x4 per thread)
        float s[4][4] = {};
        #pragma unroll 8
        for (int kk = 0; kk < 64; kk++) {
            float a[4], bb[4];
            #pragma unroll
            for (int i = 0; i < 4; i++) a[i] = qs[(ty * 4 + i) * AT_PAD + kk];
            #pragma unroll
            for (int j = 0; j < 4; j++) bb[j] = ks[(tx * 4 + j) * AT_PAD + kk];
            #pragma unroll
            for (int i = 0; i < 4; i++)
                #pragma unroll
                for (int j = 0; j < 4; j++)
                    s[i][j] = fmaf(a[i], bb[j], s[i][j]);
        }

        // Online softmax per row
        #pragma unroll
        for (int i = 0; i < 4; i++) {
            float rm = -1e30f;
            #pragma unroll
            for (int j = 0; j < 4; j++) {
                s[i][j] *= scale;
                rm = fmaxf(rm, s[i][j]);
            }
            #pragma unroll
            for (int o = 8; o >= 1; o >>= 1)
                rm = fmaxf(rm, __shfl_xor_sync(0xffffffffu, rm, o, 16));

            float mn    = fmaxf(m[i], rm);
            float alpha = __expf(m[i] - mn);
            float rs    = 0.f;
            #pragma unroll
            for (int j = 0; j < 4; j++) {
                float p = __expf(s[i][j] - mn);
                s[i][j] = p;
                rs += p;
            }
            #pragma unroll
            for (int o = 8; o >= 1; o >>= 1)
                rs += __shfl_xor_sync(0xffffffffu, rs, o, 16);

            l[i] = l[i] * alpha + rs;
            m[i] = mn;
            #pragma unroll
            for (int j = 0; j < 4; j++) acc[i][j] *= alpha;
            // stage P to smem for the PV GEMM
            #pragma unroll
            for (int j = 0; j < 4; j++)
                ps[(ty * 4 + i) * AT_PAD + tx * 4 + j] = s[i][j];
        }
        __syncthreads();

        // acc += P @ V
        #pragma unroll 8
        for (int c = 0; c < 64; c++) {
            float p4[4], v4[4];
            #pragma unroll
            for (int i = 0; i < 4; i++) p4[i] = ps[(ty * 4 + i) * AT_PAD + c];
            #pragma unroll
            for (int j = 0; j < 4; j++) v4[j] = vs[c * AT_PAD + tx * 4 + j];
            #pragma unroll
            for (int i = 0; i < 4; i++)
                #pragma unroll
                for (int j = 0; j < 4; j++)
                    acc[i][j] = fmaf(p4[i], v4[j], acc[i][j]);
        }
    }

    // Epilogue: normalize and write ctx in [B, S, H*HD] layout
    #pragma unroll
    for (int i = 0; i < 4; i++) {
        float inv = 1.0f / l[i];
        int sg = s0 + ty * 4 + i;
        #pragma unroll
        for (int j = 0; j < 4; j++) {
            int d = tx * 4 + j;
            ctx[((size_t)(b * S_ + sg)) * D_ + h * HD_ + d] = acc[i][j] * inv;
        }
    }
}

// ---------------------------------------------------------------------------

extern "C" void kernel_launch(void* const* d_in, const int* in_sizes, int n_in,
                              void* d_out, int out_size) {
    const float* query = (const float*)d_in[0];
    const float* key   = (const float*)d_in[1];
    const float* value = (const float*)d_in[2];
    const float* Wq    = (const float*)d_in[3];
    const float* bq    = (const float*)d_in[4];
    const float* Wk    = (const float*)d_in[5];
    const float* bk    = (const float*)d_in[6];
    const float* Wv    = (const float*)d_in[7];
    const float* bv    = (const float*)d_in[8];
    const float* Wo    = (const float*)d_in[9];
    const float* bo    = (const float*)d_in[10];
    float* out = (float*)d_out;

    float *qb, *kb, *vb, *ctx;
    cudaGetSymbolAddress((void**)&qb,  g_q);
    cudaGetSymbolAddress((void**)&kb,  g_k);
    cudaGetSymbolAddress((void**)&vb,  g_v);
    cudaGetSymbolAddress((void**)&ctx, g_ctx);

    const size_t attn_smem = ATTN_SMEM_FLOATS * sizeof(float);  // 66560 B
    cudaFuncSetAttribute(attn_kernel,
                         cudaFuncAttributeMaxDynamicSharedMemorySize,
                         (int)attn_smem);

    dim3 gGrid(M_ / 64, D_ / 64);  // (64, 16)
    dim3 blk(256);

    // Q/K/V projections (head-wise GEMMs)
    gemm64_kernel<true><<<gGrid, blk>>>(query, Wq, bq, qb, D_, D_);
    gemm64_kernel<true><<<gGrid, blk>>>(key,   Wk, bk, kb, D_, D_);
    gemm64_kernel<true><<<gGrid, blk>>>(value, Wv, bv, vb, D_, D_);

    // Attention
    dim3 aGrid(S_ / 64, B_ * H_);  // (32, 32)
    attn_kernel<<<aGrid, blk, attn_smem>>>(ctx);

    // Output projection
    gemm64_kernel<false><<<gGrid, blk>>>(ctx, Wo, bo, out, D_, D_);
}

// round 5
// speedup vs baseline: 1.9653x; 1.9653x over previous
#include <cuda_runtime.h>
#include <math.h>
#include <stdint.h>

#define B_  2
#define S_  2048
#define D_  1024
#define H_  16
#define HD_ 64
#define M_  (B_ * S_)        // 4096
#define BHS (B_ * H_ * S_ * HD_)

// Scratch (device globals — no allocation inside kernel_launch)
__device__ float g_q[BHS];
__device__ float g_k[BHS];
__device__ float g_v[BHS];
__device__ float g_ctx[M_ * D_];

// ---------------------------------------------------------------------------
// tf32 helpers
// ---------------------------------------------------------------------------
__device__ __forceinline__ uint32_t f2tf(float x) {
    uint32_t r;
    asm("cvt.rna.tf32.f32 %0, %1;" : "=r"(r) : "f"(x));
    return r;
}

// D += A(16x8,row) * B(8x8,col)  tf32 -> f32
__device__ __forceinline__ void mma8(float* d, const uint32_t* a, const uint32_t* b) {
    asm volatile(
        "mma.sync.aligned.m16n8k8.row.col.f32.tf32.tf32.f32 "
        "{%0,%1,%2,%3}, {%4,%5,%6,%7}, {%8,%9}, {%0,%1,%2,%3};\n"
        : "+f"(d[0]), "+f"(d[1]), "+f"(d[2]), "+f"(d[3])
        : "r"(a[0]), "r"(a[1]), "r"(a[2]), "r"(a[3]),
          "r"(b[0]), "r"(b[1]));
}

// ---------------------------------------------------------------------------
// Tensor-core GEMM: C[M,N] = A[M,K] @ W + bias
//  HEADWISE=true : W is [H,K,64], output scattered to [B,H,S,HD]; BN=64 == head.
//  TRI=true      : 3xTF32 split (fp32-class accuracy).
//  Tile 128x64, BK=16, 256 threads (8 warps, 4x2), 32x32 per warp.
// ---------------------------------------------------------------------------
template <bool HEADWISE, bool TRI>
__global__ __launch_bounds__(256)
void gemm_tc(const float* __restrict__ A, const float* __restrict__ W,
             const float* __restrict__ bias, float* __restrict__ C,
             int K, int N) {
    __shared__ float As[128][17];
    __shared__ float Bs[16][68];

    const int tid  = threadIdx.x;
    const int lane = tid & 31, wid = tid >> 5;
    const int grp  = lane >> 2, tg = lane & 3;
    const int wm   = wid >> 1, wn = wid & 1;       // 4 x 2 warp grid
    const int m0   = blockIdx.x * 128, n0 = blockIdx.y * 64;

    float acc[2][4][4];
    #pragma unroll
    for (int mi = 0; mi < 2; mi++)
        #pragma unroll
        for (int ni = 0; ni < 4; ni++)
            #pragma unroll
            for (int r = 0; r < 4; r++) acc[mi][ni][r] = 0.f;

    for (int kt = 0; kt < K; kt += 16) {
        // A tile: 128x16
        #pragma unroll
        for (int j = 0; j < 2; j++) {
            int f = j * 256 + tid;
            int r = f >> 2, c4 = (f & 3) * 4;
            float4 v = *(const float4*)(A + (size_t)(m0 + r) * K + kt + c4);
            As[r][c4] = v.x; As[r][c4+1] = v.y; As[r][c4+2] = v.z; As[r][c4+3] = v.w;
        }
        // B tile: 16x64
        {
            int r = tid >> 4, c4 = (tid & 15) * 4;
            const float* src = HEADWISE
                ? W + ((size_t)(n0 >> 6) * K + kt + r) * 64 + c4
                : W + (size_t)(kt + r) * N + n0 + c4;
            float4 v = *(const float4*)src;
            Bs[r][c4] = v.x; Bs[r][c4+1] = v.y; Bs[r][c4+2] = v.z; Bs[r][c4+3] = v.w;
        }
        __syncthreads();

        #pragma unroll
        for (int ks = 0; ks < 16; ks += 8) {
            uint32_t ah[2][4], al[2][4];
            #pragma unroll
            for (int mi = 0; mi < 2; mi++) {
                int r0 = wm * 32 + mi * 16;
                float v0 = As[r0 + grp][ks + tg];
                float v1 = As[r0 + grp + 8][ks + tg];
                float v2 = As[r0 + grp][ks + tg + 4];
                float v3 = As[r0 + grp + 8][ks + tg + 4];
                ah[mi][0] = f2tf(v0); ah[mi][1] = f2tf(v1);
                ah[mi][2] = f2tf(v2); ah[mi][3] = f2tf(v3);
                if (TRI) {
                    al[mi][0] = f2tf(v0 - __uint_as_float(ah[mi][0]));
                    al[mi][1] = f2tf(v1 - __uint_as_float(ah[mi][1]));
                    al[mi][2] = f2tf(v2 - __uint_as_float(ah[mi][2]));
                    al[mi][3] = f2tf(v3 - __uint_as_float(ah[mi][3]));
                }
            }
            uint32_t bh[4][2], bl[4][2];
            #pragma unroll
            for (int ni = 0; ni < 4; ni++) {
                int c = wn * 32 + ni * 8 + grp;
                float w0 = Bs[ks + tg][c];
                float w1 = Bs[ks + tg + 4][c];
                bh[ni][0] = f2tf(w0); bh[ni][1] = f2tf(w1);
                if (TRI) {
                    bl[ni][0] = f2tf(w0 - __uint_as_float(bh[ni][0]));
                    bl[ni][1] = f2tf(w1 - __uint_as_float(bh[ni][1]));
                }
            }
            #pragma unroll
            for (int mi = 0; mi < 2; mi++)
                #pragma unroll
                for (int ni = 0; ni < 4; ni++) {
                    mma8(acc[mi][ni], ah[mi], bh[ni]);
                    if (TRI) {
                        mma8(acc[mi][ni], al[mi], bh[ni]);
                        mma8(acc[mi][ni], ah[mi], bl[ni]);
                    }
                }
        }
        __syncthreads();
    }

    // Epilogue
    #pragma unroll
    for (int mi = 0; mi < 2; mi++) {
        #pragma unroll
        for (int ni = 0; ni < 4; ni++) {
            int n  = n0 + wn * 32 + ni * 8 + tg * 2;
            float b0 = bias[n], b1 = bias[n + 1];
            #pragma unroll
            for (int half = 0; half < 2; half++) {
                int m = m0 + wm * 32 + mi * 16 + grp + half * 8;
                float v0 = acc[mi][ni][half * 2 + 0] + b0;
                float v1 = acc[mi][ni][half * 2 + 1] + b1;
                if (HEADWISE) {
                    int bb = m / S_, s = m - bb * S_;
                    int hh = n >> 6, k = n & 63;
                    float* dst = C + (((size_t)(bb * H_ + hh)) * S_ + s) * HD_ + k;
                    dst[0] = v0; dst[1] = v1;
                } else {
                    C[(size_t)m * N + n]     = v0;
                    C[(size_t)m * N + n + 1] = v1;
                }
            }
        }
    }
}

// ---------------------------------------------------------------------------
// Flash attention with tf32 mma (1x): 64 q rows per CTA, 64-row K/V tiles.
// Warp grid 4(M)x2(N): each warp 16q x 32cols (1 m16 tile x 4 n8 tiles).
// Scores round-trip through smem for softmax + PV A-operand.
// ---------------------------------------------------------------------------
#define AP 68
#define ATTN_SMEM ((4 * 64 * AP + 64) * (int)sizeof(float))   // 69888 B

__global__ __launch_bounds__(256)
void attn_tc(float* __restrict__ ctx) {
    extern __shared__ float sm[];
    float* qs     = sm;                 // [64][68]
    float* ks     = qs + 64 * AP;       // [64][68]
    float* vs     = ks + 64 * AP;       // [64][68]
    float* ps     = vs + 64 * AP;       // [64][68]  scores -> probs
    float* rowbuf = ps + 64 * AP;       // [64]      alpha / 1/l

    const int tid  = threadIdx.x;
    const int lane = tid & 31, wid = tid >> 5;
    const int grp  = lane >> 2, tg = lane & 3;
    const int wm   = wid >> 1, wn = wid & 1;
    const int bh   = blockIdx.y;
    const int b    = bh >> 4, h = bh & 15;
    const int s0   = blockIdx.x * 64;

    const float* Qp = g_q + (size_t)bh * S_ * HD_;
    const float* Kp = g_k + (size_t)bh * S_ * HD_;
    const float* Vp = g_v + (size_t)bh * S_ * HD_;

    // Q tile
    #pragma unroll
    for (int j = 0; j < 4; j++) {
        int f = j * 256 + tid;
        int r = f >> 4, c4 = (f & 15) * 4;
        float4 v = *(const float4*)(Qp + (size_t)(s0 + r) * HD_ + c4);
        qs[r*AP+c4] = v.x; qs[r*AP+c4+1] = v.y; qs[r*AP+c4+2] = v.z; qs[r*AP+c4+3] = v.w;
    }

    float mrun = -1e30f, lrun = 0.f;    // softmax state for row (tid>>2)
    float octx[4][4];
    #pragma unroll
    for (int ni = 0; ni < 4; ni++)
        #pragma unroll
        for (int r = 0; r < 4; r++) octx[ni][r] = 0.f;

    const float scale = 0.125f;         // 1/sqrt(64)

    for (int kt = 0; kt < S_; kt += 64) {
        __syncthreads();                // prior PV done with ks/vs/ps
        #pragma unroll
        for (int j = 0; j < 4; j++) {
            int f = j * 256 + tid;
            int r = f >> 4, c4 = (f & 15) * 4;
            float4 kv = *(const float4*)(Kp + (size_t)(kt + r) * HD_ + c4);
            ks[r*AP+c4] = kv.x; ks[r*AP+c4+1] = kv.y; ks[r*AP+c4+2] = kv.z; ks[r*AP+c4+3] = kv.w;
            float4 vv = *(const float4*)(Vp + (size_t)(kt + r) * HD_ + c4);
            vs[r*AP+c4] = vv.x; vs[r*AP+c4+1] = vv.y; vs[r*AP+c4+2] = vv.z; vs[r*AP+c4+3] = vv.w;
        }
        __syncthreads();

        // S = Q K^T
        float sacc[4][4];
        #pragma unroll
        for (int ni = 0; ni < 4; ni++)
            #pragma unroll
            for (int r = 0; r < 4; r++) sacc[ni][r] = 0.f;

        #pragma unroll
        for (int kk = 0; kk < 64; kk += 8) {
            uint32_t af[4];
            int r0 = wm * 16;
            af[0] = f2tf(qs[(r0+grp  )*AP + kk+tg  ]);
            af[1] = f2tf(qs[(r0+grp+8)*AP + kk+tg  ]);
            af[2] = f2tf(qs[(r0+grp  )*AP + kk+tg+4]);
            af[3] = f2tf(qs[(r0+grp+8)*AP + kk+tg+4]);
            #pragma unroll
            for (int ni = 0; ni < 4; ni++) {
                int c = wn * 32 + ni * 8 + grp;
                uint32_t bf[2];
                bf[0] = f2tf(ks[c*AP + kk+tg  ]);
                bf[1] = f2tf(ks[c*AP + kk+tg+4]);
                mma8(sacc[ni], af, bf);
            }
        }
        // scaled scores -> smem
        #pragma unroll
        for (int ni = 0; ni < 4; ni++) {
            int c = wn * 32 + ni * 8 + tg * 2;
            int r = wm * 16 + grp;
            *(float2*)(ps + r*AP + c)     = make_float2(sacc[ni][0]*scale, sacc[ni][1]*scale);
            *(float2*)(ps + (r+8)*AP + c) = make_float2(sacc[ni][2]*scale, sacc[ni][3]*scale);
        }
        __syncthreads();

        // online softmax: 4 threads per row, 16 cols each
        {
            int row = tid >> 2, q4 = tid & 3;
            float* pr = ps + row * AP + q4 * 16;
            float t[16];
            float rm = -1e30f;
            #pragma unroll
            for (int j = 0; j < 16; j++) { t[j] = pr[j]; rm = fmaxf(rm, t[j]); }
            rm = fmaxf(rm, __shfl_xor_sync(0xffffffffu, rm, 1, 4));
            rm = fmaxf(rm, __shfl_xor_sync(0xffffffffu, rm, 2, 4));
            float mn    = fmaxf(mrun, rm);
            float alpha = __expf(mrun - mn);
            float rs = 0.f;
            #pragma unroll
            for (int j = 0; j < 16; j++) {
                float p = __expf(t[j] - mn);
                pr[j] = p;
                rs += p;
            }
            rs += __shfl_xor_sync(0xffffffffu, rs, 1, 4);
            rs += __shfl_xor_sync(0xffffffffu, rs, 2, 4);
            lrun = lrun * alpha + rs;
            mrun = mn;
            if (q4 == 0) rowbuf[row] = alpha;
        }
        __syncthreads();

        // rescale running ctx by alpha(row)
        {
            float a0 = rowbuf[wm * 16 + grp];
            float a1 = rowbuf[wm * 16 + grp + 8];
            #pragma unroll
            for (int ni = 0; ni < 4; ni++) {
                octx[ni][0] *= a0; octx[ni][1] *= a0;
                octx[ni][2] *= a1; octx[ni][3] *= a1;
            }
        }

        // octx += P @ V
        #pragma unroll
        for (int kk = 0; kk < 64; kk += 8) {
            uint32_t af[4];
            int r0 = wm * 16;
            af[0] = f2tf(ps[(r0+grp  )*AP + kk+tg  ]);
            af[1] = f2tf(ps[(r0+grp+8)*AP + kk+tg  ]);
            af[2] = f2tf(ps[(r0+grp  )*AP + kk+tg+4]);
            af[3] = f2tf(ps[(r0+grp+8)*AP + kk+tg+4]);
            #pragma unroll
            for (int ni = 0; ni < 4; ni++) {
                int c = wn * 32 + ni * 8 + grp;
                uint32_t bf[2];
                bf[0] = f2tf(vs[(kk+tg  )*AP + c]);
                bf[1] = f2tf(vs[(kk+tg+4)*AP + c]);
                mma8(octx[ni], af, bf);
            }
        }
    }

    __syncthreads();
    if ((tid & 3) == 0) rowbuf[tid >> 2] = 1.0f / lrun;
    __syncthreads();

    // write ctx in [B, S, H*HD] layout
    {
        float l0 = rowbuf[wm * 16 + grp];
        float l1 = rowbuf[wm * 16 + grp + 8];
        int sg0 = s0 + wm * 16 + grp;
        #pragma unroll
        for (int ni = 0; ni < 4; ni++) {
            int c = wn * 32 + ni * 8 + tg * 2;
            *(float2*)(ctx + ((size_t)(b * S_ + sg0    )) * D_ + h * HD_ + c)
                = make_float2(octx[ni][0] * l0, octx[ni][1] * l0);
            *(float2*)(ctx + ((size_t)(b * S_ + sg0 + 8)) * D_ + h * HD_ + c)
                = make_float2(octx[ni][2] * l1, octx[ni][3] * l1);
        }
    }
}

// ---------------------------------------------------------------------------

extern "C" void kernel_launch(void* const* d_in, const int* in_sizes, int n_in,
                              void* d_out, int out_size) {
    const float* query = (const float*)d_in[0];
    const float* key   = (const float*)d_in[1];
    const float* value = (const float*)d_in[2];
    const float* Wq    = (const float*)d_in[3];
    const float* bq    = (const float*)d_in[4];
    const float* Wk    = (const float*)d_in[5];
    const float* bk    = (const float*)d_in[6];
    const float* Wv    = (const float*)d_in[7];
    const float* bv    = (const float*)d_in[8];
    const float* Wo    = (const float*)d_in[9];
    const float* bo    = (const float*)d_in[10];
    float* out = (float*)d_out;

    float *qb, *kb, *vb, *ctx;
    cudaGetSymbolAddress((void**)&qb,  g_q);
    cudaGetSymbolAddress((void**)&kb,  g_k);
    cudaGetSymbolAddress((void**)&vb,  g_v);
    cudaGetSymbolAddress((void**)&ctx, g_ctx);

    cudaFuncSetAttribute(attn_tc,
                         cudaFuncAttributeMaxDynamicSharedMemorySize,
                         ATTN_SMEM);

    dim3 blk(256);
    dim3 pGrid(M_ / 128, D_ / 64);   // 32 x 16

    // Q/K/V projections — 3xTF32 (fp32-class accuracy)
    gemm_tc<true,  true><<<pGrid, blk>>>(query, Wq, bq, qb, D_, D_);
    gemm_tc<true,  true><<<pGrid, blk>>>(key,   Wk, bk, kb, D_, D_);
    gemm_tc<true,  true><<<pGrid, blk>>>(value, Wv, bv, vb, D_, D_);

    // Attention — 1xTF32 mma
    dim3 aGrid(S_ / 64, B_ * H_);    // (32, 32)
    attn_tc<<<aGrid, blk, ATTN_SMEM>>>(ctx);

    // Output projection — 3xTF32
    gemm_tc<false, true><<<pGrid, blk>>>(ctx, Wo, bo, out, D_, D_);
}

// round 6
// speedup vs baseline: 3.0736x; 1.5639x over previous
#include <cuda_runtime.h>
#include <cuda_bf16.h>
#include <math.h>
#include <stdint.h>

#define B_  2
#define S_  2048
#define D_  1024
#define H_  16
#define HD_ 64
#define M_  (B_ * S_)        // 4096
#define BHS (B_ * H_ * S_ * HD_)

// Scratch (device globals — no allocation inside kernel_launch)
__device__ float g_q[BHS];
__device__ float g_k[BHS];
__device__ float g_v[BHS];
__device__ float g_ctx[M_ * D_];

// ---------------------------------------------------------------------------
// helpers
// ---------------------------------------------------------------------------
__device__ __forceinline__ uint32_t f2tf(float x) {
    uint32_t r;
    asm("cvt.rna.tf32.f32 %0, %1;" : "=r"(r) : "f"(x));
    return r;
}

// tf32 mma: D += A(16x8) * B(8x8)
__device__ __forceinline__ void mma8(float* d, const uint32_t* a, const uint32_t* b) {
    asm volatile(
        "mma.sync.aligned.m16n8k8.row.col.f32.tf32.tf32.f32 "
        "{%0,%1,%2,%3}, {%4,%5,%6,%7}, {%8,%9}, {%0,%1,%2,%3};\n"
        : "+f"(d[0]), "+f"(d[1]), "+f"(d[2]), "+f"(d[3])
        : "r"(a[0]), "r"(a[1]), "r"(a[2]), "r"(a[3]),
          "r"(b[0]), "r"(b[1]));
}

// bf16 mma: D += A(16x16) * B(16x8)
__device__ __forceinline__ void mma16(float* d, const uint32_t* a, const uint32_t* b) {
    asm volatile(
        "mma.sync.aligned.m16n8k16.row.col.f32.bf16.bf16.f32 "
        "{%0,%1,%2,%3}, {%4,%5,%6,%7}, {%8,%9}, {%0,%1,%2,%3};\n"
        : "+f"(d[0]), "+f"(d[1]), "+f"(d[2]), "+f"(d[3])
        : "r"(a[0]), "r"(a[1]), "r"(a[2]), "r"(a[3]),
          "r"(b[0]), "r"(b[1]));
}

__device__ __forceinline__ void ldsm4t(uint32_t& t0, uint32_t& t1,
                                       uint32_t& t2, uint32_t& t3,
                                       const void* p) {
    uint32_t saddr = (uint32_t)__cvta_generic_to_shared(p);
    asm volatile("ldmatrix.sync.aligned.m8n8.x4.trans.shared.b16 "
                 "{%0,%1,%2,%3}, [%4];"
                 : "=r"(t0), "=r"(t1), "=r"(t2), "=r"(t3) : "r"(saddr));
}

// split two floats into packed bf16x2 hi and lo words (element 0 = lower half)
__device__ __forceinline__ void split2(float x0, float x1,
                                       uint32_t& hi, uint32_t& lo) {
    __nv_bfloat16 h0 = __float2bfloat16_rn(x0);
    __nv_bfloat16 h1 = __float2bfloat16_rn(x1);
    __nv_bfloat16 l0 = __float2bfloat16_rn(x0 - __bfloat162float(h0));
    __nv_bfloat16 l1 = __float2bfloat16_rn(x1 - __bfloat162float(h1));
    __nv_bfloat162 hp = __halves2bfloat162(h0, h1);
    __nv_bfloat162 lp = __halves2bfloat162(l0, l1);
    hi = *reinterpret_cast<uint32_t*>(&hp);
    lo = *reinterpret_cast<uint32_t*>(&lp);
}

// ---------------------------------------------------------------------------
// GEMM via 3-term bf16 split: C[M,N] = A[M,K] @ W + bias  (fp32-class accuracy)
//  HEADWISE=true : W is [H,K,64], output scattered to [B,H,S,HD]; BN=64 == head.
//  Tile 128x64, BK=32, 256 threads (8 warps, 4x2), 32x32 per warp.
//  A fragments via scalar LDS.32 (packed bf16x2), B via ldmatrix.x4.trans.
// ---------------------------------------------------------------------------
#define AW 20   // Ah/Al row stride in words (32 bf16 = 16 words + 4 pad)
#define BW 72   // Bh/Bl row stride in bf16 (64 + 8 pad); 144 B, 16B-aligned

template <bool HEADWISE>
__global__ __launch_bounds__(256)
void gemm_bf3(const float* __restrict__ A, const float* __restrict__ W,
              const float* __restrict__ bias, float* __restrict__ C,
              int K, int N) {
    __shared__ __align__(16) uint32_t Ah[128][AW];
    __shared__ __align__(16) uint32_t Al[128][AW];
    __shared__ __align__(16) __nv_bfloat16 Bh[32][BW];
    __shared__ __align__(16) __nv_bfloat16 Bl[32][BW];

    const int tid  = threadIdx.x;
    const int lane = tid & 31, wid = tid >> 5;
    const int grp  = lane >> 2, tg = lane & 3;
    const int wm   = wid >> 1, wn = wid & 1;        // 4 x 2 warp grid
    const int m0   = blockIdx.x * 128, n0 = blockIdx.y * 64;

    float acc[2][4][4];
    #pragma unroll
    for (int mi = 0; mi < 2; mi++)
        #pragma unroll
        for (int ni = 0; ni < 4; ni++)
            #pragma unroll
            for (int r = 0; r < 4; r++) acc[mi][ni][r] = 0.f;

    for (int kt = 0; kt < K; kt += 32) {
        // A tile: 128 x 32 fp32 -> bf16 hi/lo packed pairs
        #pragma unroll
        for (int j = 0; j < 4; j++) {
            int f = j * 256 + tid;
            int r = f >> 3, c = f & 7;              // c: float4 chunk (k = 4c)
            float4 v = *(const float4*)(A + (size_t)(m0 + r) * K + kt + c * 4);
            uint32_t h0, l0, h1, l1;
            split2(v.x, v.y, h0, l0);
            split2(v.z, v.w, h1, l1);
            Ah[r][2 * c]     = h0;  Ah[r][2 * c + 1] = h1;
            Al[r][2 * c]     = l0;  Al[r][2 * c + 1] = l1;
        }
        // B tile: 32 x 64 fp32 -> bf16 hi/lo
        #pragma unroll
        for (int j = 0; j < 2; j++) {
            int f = j * 256 + tid;
            int r = f >> 4, c4 = (f & 15) * 4;
            const float* src = HEADWISE
                ? W + ((size_t)(n0 >> 6) * K + kt + r) * 64 + c4
                : W + (size_t)(kt + r) * N + n0 + c4;
            float4 v = *(const float4*)src;
            uint32_t h0, l0, h1, l1;
            split2(v.x, v.y, h0, l0);
            split2(v.z, v.w, h1, l1);
            *(uint32_t*)&Bh[r][c4]     = h0;  *(uint32_t*)&Bh[r][c4 + 2] = h1;
            *(uint32_t*)&Bl[r][c4]     = l0;  *(uint32_t*)&Bl[r][c4 + 2] = l1;
        }
        __syncthreads();

        #pragma unroll
        for (int kk = 0; kk < 32; kk += 16) {
            const int w = kk >> 1;
            uint32_t fah[2][4], fal[2][4];
            #pragma unroll
            for (int mi = 0; mi < 2; mi++) {
                int r0 = wm * 32 + mi * 16;
                fah[mi][0] = Ah[r0 + grp][w + tg];
                fah[mi][1] = Ah[r0 + grp + 8][w + tg];
                fah[mi][2] = Ah[r0 + grp][w + tg + 4];
                fah[mi][3] = Ah[r0 + grp + 8][w + tg + 4];
                fal[mi][0] = Al[r0 + grp][w + tg];
                fal[mi][1] = Al[r0 + grp + 8][w + tg];
                fal[mi][2] = Al[r0 + grp][w + tg + 4];
                fal[mi][3] = Al[r0 + grp + 8][w + tg + 4];
            }
            uint32_t fbh[4][2], fbl[4][2];
            {
                int g = lane >> 3, r = lane & 7;
                int krow = kk + (g & 1) * 8 + r;
                #pragma unroll
                for (int nblk = 0; nblk < 2; nblk++) {
                    int col = wn * 32 + nblk * 16 + (g >> 1) * 8;
                    uint32_t t0, t1, t2, t3;
                    ldsm4t(t0, t1, t2, t3, &Bh[krow][col]);
                    fbh[nblk * 2][0] = t0;  fbh[nblk * 2][1] = t1;
                    fbh[nblk * 2 + 1][0] = t2;  fbh[nblk * 2 + 1][1] = t3;
                    ldsm4t(t0, t1, t2, t3, &Bl[krow][col]);
                    fbl[nblk * 2][0] = t0;  fbl[nblk * 2][1] = t1;
                    fbl[nblk * 2 + 1][0] = t2;  fbl[nblk * 2 + 1][1] = t3;
                }
            }
            #pragma unroll
            for (int mi = 0; mi < 2; mi++)
                #pragma unroll
                for (int ni = 0; ni < 4; ni++) {
                    mma16(acc[mi][ni], fah[mi], fbh[ni]);
                    mma16(acc[mi][ni], fah[mi], fbl[ni]);
                    mma16(acc[mi][ni], fal[mi], fbh[ni]);
                }
        }
        __syncthreads();
    }

    // Epilogue
    #pragma unroll
    for (int mi = 0; mi < 2; mi++) {
        #pragma unroll
        for (int ni = 0; ni < 4; ni++) {
            int n  = n0 + wn * 32 + ni * 8 + tg * 2;
            float b0 = bias[n], b1 = bias[n + 1];
            #pragma unroll
            for (int half = 0; half < 2; half++) {
                int m = m0 + wm * 32 + mi * 16 + grp + half * 8;
                float v0 = acc[mi][ni][half * 2 + 0] + b0;
                float v1 = acc[mi][ni][half * 2 + 1] + b1;
                if (HEADWISE) {
                    int bb = m / S_, s = m - bb * S_;
                    int hh = n >> 6, k = n & 63;
                    float* dst = C + (((size_t)(bb * H_ + hh)) * S_ + s) * HD_ + k;
                    dst[0] = v0; dst[1] = v1;
                } else {
                    C[(size_t)m * N + n]     = v0;
                    C[(size_t)m * N + n + 1] = v1;
                }
            }
        }
    }
}

// ---------------------------------------------------------------------------
// Flash attention, tf32 mma, pre-converted smem operands.
// 128 q rows per CTA, 64-row K/V tiles. 8 warps 4(M)x2(N), warp = 32q x 32c.
// Scale folded into Q at load. P written back tf32-rounded.
// ---------------------------------------------------------------------------
#define AP 68
#define ATTN_SMEM (((128 + 64 + 64 + 128) * AP + 128) * (int)sizeof(float))

__global__ __launch_bounds__(256)
void attn_tc(float* __restrict__ ctx) {
    extern __shared__ float sm[];
    float* qs     = sm;                  // [128][68] tf32 (pre-scaled)
    float* ks     = qs + 128 * AP;       // [64][68]  tf32
    float* vs     = ks + 64 * AP;        // [64][68]  tf32
    float* ps     = vs + 64 * AP;        // [128][68] scores (fp32) -> probs (tf32)
    float* rowbuf = ps + 128 * AP;       // [128]     alpha / 1/l

    const int tid  = threadIdx.x;
    const int lane = tid & 31, wid = tid >> 5;
    const int grp  = lane >> 2, tg = lane & 3;
    const int wm   = wid >> 1, wn = wid & 1;
    const int bh   = blockIdx.y;
    const int b    = bh >> 4, h = bh & 15;
    const int s0   = blockIdx.x * 128;

    const float* Qp = g_q + (size_t)bh * S_ * HD_;
    const float* Kp = g_k + (size_t)bh * S_ * HD_;
    const float* Vp = g_v + (size_t)bh * S_ * HD_;

    const float scale = 0.125f;          // 1/sqrt(64), folded into Q

    // Q tile (128 x 64), scaled + tf32-converted
    #pragma unroll
    for (int j = 0; j < 8; j++) {
        int f = j * 256 + tid;
        int r = f >> 4, c4 = (f & 15) * 4;
        float4 v = *(const float4*)(Qp + (size_t)(s0 + r) * HD_ + c4);
        float* d = qs + r * AP + c4;
        d[0] = __uint_as_float(f2tf(v.x * scale));
        d[1] = __uint_as_float(f2tf(v.y * scale));
        d[2] = __uint_as_float(f2tf(v.z * scale));
        d[3] = __uint_as_float(f2tf(v.w * scale));
    }

    float mrun = -1e30f, lrun = 0.f;     // softmax state: row = tid>>1
    float octx[2][4][4];
    #pragma unroll
    for (int mi = 0; mi < 2; mi++)
        #pragma unroll
        for (int ni = 0; ni < 4; ni++)
            #pragma unroll
            for (int r = 0; r < 4; r++) octx[mi][ni][r] = 0.f;

    for (int kt = 0; kt < S_; kt += 64) {
        __syncthreads();                 // prior PV done with ks/vs/ps
        #pragma unroll
        for (int j = 0; j < 4; j++) {
            int f = j * 256 + tid;
            int r = f >> 4, c4 = (f & 15) * 4;
            float4 kv = *(const float4*)(Kp + (size_t)(kt + r) * HD_ + c4);
            float* dk = ks + r * AP + c4;
            dk[0] = __uint_as_float(f2tf(kv.x));
            dk[1] = __uint_as_float(f2tf(kv.y));
            dk[2] = __uint_as_float(f2tf(kv.z));
            dk[3] = __uint_as_float(f2tf(kv.w));
            float4 vv = *(const float4*)(Vp + (size_t)(kt + r) * HD_ + c4);
            float* dv = vs + r * AP + c4;
            dv[0] = __uint_as_float(f2tf(vv.x));
            dv[1] = __uint_as_float(f2tf(vv.y));
            dv[2] = __uint_as_float(f2tf(vv.z));
            dv[3] = __uint_as_float(f2tf(vv.w));
        }
        __syncthreads();

        // S = Q K^T
        float sacc[2][4][4];
        #pragma unroll
        for (int mi = 0; mi < 2; mi++)
            #pragma unroll
            for (int ni = 0; ni < 4; ni++)
                #pragma unroll
                for (int r = 0; r < 4; r++) sacc[mi][ni][r] = 0.f;

        #pragma unroll
        for (int kk = 0; kk < 64; kk += 8) {
            uint32_t af[2][4];
            #pragma unroll
            for (int mi = 0; mi < 2; mi++) {
                int r0 = wm * 32 + mi * 16;
                af[mi][0] = __float_as_uint(qs[(r0+grp  )*AP + kk+tg  ]);
                af[mi][1] = __float_as_uint(qs[(r0+grp+8)*AP + kk+tg  ]);
                af[mi][2] = __float_as_uint(qs[(r0+grp  )*AP + kk+tg+4]);
                af[mi][3] = __float_as_uint(qs[(r0+grp+8)*AP + kk+tg+4]);
            }
            #pragma unroll
            for (int ni = 0; ni < 4; ni++) {
                int c = wn * 32 + ni * 8 + grp;
                uint32_t bf[2];
                bf[0] = __float_as_uint(ks[c*AP + kk+tg  ]);
                bf[1] = __float_as_uint(ks[c*AP + kk+tg+4]);
                #pragma unroll
                for (int mi = 0; mi < 2; mi++)
                    mma8(sacc[mi][ni], af[mi], bf);
            }
        }
        // scores -> smem (fp32)
        #pragma unroll
        for (int mi = 0; mi < 2; mi++) {
            int r = wm * 32 + mi * 16 + grp;
            #pragma unroll
            for (int ni = 0; ni < 4; ni++) {
                int c = wn * 32 + ni * 8 + tg * 2;
                *(float2*)(ps + r*AP + c)     = make_float2(sacc[mi][ni][0], sacc[mi][ni][1]);
                *(float2*)(ps + (r+8)*AP + c) = make_float2(sacc[mi][ni][2], sacc[mi][ni][3]);
            }
        }
        __syncthreads();

        // online softmax: 2 threads per row, 32 cols each
        {
            int row = tid >> 1, seg = (tid & 1) * 32;
            float* pr = ps + row * AP + seg;
            float rm = -1e30f;
            #pragma unroll
            for (int j = 0; j < 32; j++) rm = fmaxf(rm, pr[j]);
            rm = fmaxf(rm, __shfl_xor_sync(0xffffffffu, rm, 1, 2));
            float mn    = fmaxf(mrun, rm);
            float alpha = __expf(mrun - mn);
            float rs = 0.f;
            #pragma unroll
            for (int j = 0; j < 32; j++) {
                float p = __expf(pr[j] - mn);
                pr[j] = __uint_as_float(f2tf(p));
                rs += p;
            }
            rs += __shfl_xor_sync(0xffffffffu, rs, 1, 2);
            lrun = lrun * alpha + rs;
            mrun = mn;
            if (!(tid & 1)) rowbuf[row] = alpha;
        }
        __syncthreads();

        // rescale running ctx
        #pragma unroll
        for (int mi = 0; mi < 2; mi++) {
            int r0 = wm * 32 + mi * 16;
            float a0 = rowbuf[r0 + grp];
            float a1 = rowbuf[r0 + grp + 8];
            #pragma unroll
            for (int ni = 0; ni < 4; ni++) {
                octx[mi][ni][0] *= a0; octx[mi][ni][1] *= a0;
                octx[mi][ni][2] *= a1; octx[mi][ni][3] *= a1;
            }
        }

        // octx += P @ V
        #pragma unroll
        for (int kk = 0; kk < 64; kk += 8) {
            uint32_t af[2][4];
            #pragma unroll
            for (int mi = 0; mi < 2; mi++) {
                int r0 = wm * 32 + mi * 16;
                af[mi][0] = __float_as_uint(ps[(r0+grp  )*AP + kk+tg  ]);
                af[mi][1] = __float_as_uint(ps[(r0+grp+8)*AP + kk+tg  ]);
                af[mi][2] = __float_as_uint(ps[(r0+grp  )*AP + kk+tg+4]);
                af[mi][3] = __float_as_uint(ps[(r0+grp+8)*AP + kk+tg+4]);
            }
            #pragma unroll
            for (int ni = 0; ni < 4; ni++) {
                int c = wn * 32 + ni * 8 + grp;
                uint32_t bf[2];
                bf[0] = __float_as_uint(vs[(kk+tg  )*AP + c]);
                bf[1] = __float_as_uint(vs[(kk+tg+4)*AP + c]);
                #pragma unroll
                for (int mi = 0; mi < 2; mi++)
                    mma8(octx[mi][ni], af[mi], bf);
            }
        }
    }

    __syncthreads();
    if (!(tid & 1)) rowbuf[tid >> 1] = 1.0f / lrun;
    __syncthreads();

    // write ctx in [B, S, H*HD] layout
    #pragma unroll
    for (int mi = 0; mi < 2; mi++) {
        int r0 = wm * 32 + mi * 16;
        float l0 = rowbuf[r0 + grp];
        float l1 = rowbuf[r0 + grp + 8];
        int sg0 = s0 + r0 + grp;
        #pragma unroll
        for (int ni = 0; ni < 4; ni++) {
            int c = wn * 32 + ni * 8 + tg * 2;
            *(float2*)(ctx + ((size_t)(b * S_ + sg0    )) * D_ + h * HD_ + c)
                = make_float2(octx[mi][ni][0] * l0, octx[mi][ni][1] * l0);
            *(float2*)(ctx + ((size_t)(b * S_ + sg0 + 8)) * D_ + h * HD_ + c)
                = make_float2(octx[mi][ni][2] * l1, octx[mi][ni][3] * l1);
        }
    }
}

// ---------------------------------------------------------------------------

extern "C" void kernel_launch(void* const* d_in, const int* in_sizes, int n_in,
                              void* d_out, int out_size) {
    const float* query = (const float*)d_in[0];
    const float* key   = (const float*)d_in[1];
    const float* value = (const float*)d_in[2];
    const float* Wq    = (const float*)d_in[3];
    const float* bq    = (const float*)d_in[4];
    const float* Wk    = (const float*)d_in[5];
    const float* bk    = (const float*)d_in[6];
    const float* Wv    = (const float*)d_in[7];
    const float* bv    = (const float*)d_in[8];
    const float* Wo    = (const float*)d_in[9];
    const float* bo    = (const float*)d_in[10];
    float* out = (float*)d_out;

    float *qb, *kb, *vb, *ctx;
    cudaGetSymbolAddress((void**)&qb,  g_q);
    cudaGetSymbolAddress((void**)&kb,  g_k);
    cudaGetSymbolAddress((void**)&vb,  g_v);
    cudaGetSymbolAddress((void**)&ctx, g_ctx);

    cudaFuncSetAttribute(attn_tc,
                         cudaFuncAttributeMaxDynamicSharedMemorySize,
                         ATTN_SMEM);

    dim3 blk(256);
    dim3 pGrid(M_ / 128, D_ / 64);   // 32 x 16

    // Q/K/V projections — 3-term bf16 (fp32-class accuracy)
    gemm_bf3<true ><<<pGrid, blk>>>(query, Wq, bq, qb, D_, D_);
    gemm_bf3<true ><<<pGrid, blk>>>(key,   Wk, bk, kb, D_, D_);
    gemm_bf3<true ><<<pGrid, blk>>>(value, Wv, bv, vb, D_, D_);

    // Attention — 1xTF32 mma
    dim3 aGrid(S_ / 128, B_ * H_);   // (16, 32)
    attn_tc<<<aGrid, blk, ATTN_SMEM>>>(ctx);

    // Output projection — 3-term bf16
    gemm_bf3<false><<<pGrid, blk>>>(ctx, Wo, bo, out, D_, D_);
}